// round 12
// baseline (speedup 1.0000x reference)
#include <cuda_runtime.h>

// Problem constants (fixed by the dataset): N=8192, F=128, H=64, B=8
#define MAXN 8192
#define MAXB 16
#define FDIM 128
#define HDIM 64
#define NBLK (MAXN / 32)   // k_charge / k_pairs blocks (32 atoms each)

// Scratch (device globals: allocation-free rule)
__device__ float4 g_pq[MAXN];          // packed pos.xyz + RAW charge q
__device__ float  g_c[MAXN];           // |pos|^2 per atom
__device__ int    g_batch[MAXN];       // int32 batch ids
__device__ float  g_bsum[NBLK][MAXB];  // per-block per-graph raw-q partial sums

// ---------------------------------------------------------------------------
// K_A: fused charge head + batch convert + pos/q pack + per-block q sums.
//   q = silu(x@W1 + b1)@W2 + b2
// Block: 256 threads (16 tx x 16 ty) computes 32 atoms x 64 cols,
// 2x4 register tile per thread, K=128 split into two 64-tiles in shared.
// Epilogue writes DETERMINISTIC per-block graph sums (no global atomics,
// no memset node needed).
// ---------------------------------------------------------------------------
__global__ __launch_bounds__(256) void k_charge(
    const float* __restrict__ x, const float* __restrict__ pos,
    const float* __restrict__ W1, const float* __restrict__ b1,
    const float* __restrict__ W2, const float* __restrict__ b2,
    const void* __restrict__ batch, int n)
{
    __shared__ float xs[32][64];   // [atom][k]
    __shared__ float ws[64][64];   // [k][col]
    __shared__ float red[32][17];  // reduction buffer, padded
    __shared__ float w2s[HDIM], b1s[HDIM];
    __shared__ float sm_qsum[MAXB];

    int tid = threadIdx.x;
    int tx = tid & 15;        // col group  (4 cols each -> 64 cols)
    int ty = tid >> 4;        // atom group (2 atoms each -> 32 atoms)
    int ab = blockIdx.x * 32; // first atom of this block

    if (tid < HDIM) { w2s[tid] = W2[tid]; b1s[tid] = b1[tid]; }
    if (tid < MAXB) sm_qsum[tid] = 0.f;

    float acc[2][4];
#pragma unroll
    for (int i = 0; i < 2; i++)
#pragma unroll
        for (int j = 0; j < 4; j++) acc[i][j] = 0.f;

    for (int kt = 0; kt < 2; kt++) {
        int kb = kt * 64;
        __syncthreads();
        // xs: 32x64 floats = 512 float4 -> 2 per thread
#pragma unroll
        for (int it = 0; it < 2; it++) {
            int idx = tid + it * 256;     // 0..511
            int row = idx >> 4;           // 0..31
            int c4  = (idx & 15) * 4;
            float4 v = *(const float4*)&x[(ab + row) * FDIM + kb + c4];
            *(float4*)&xs[row][c4] = v;
        }
        // ws: 64x64 floats = 1024 float4 -> 4 per thread
#pragma unroll
        for (int it = 0; it < 4; it++) {
            int idx = tid + it * 256;     // 0..1023
            int row = idx >> 4;           // 0..63
            int c4  = (idx & 15) * 4;
            float4 w = *(const float4*)&W1[(kb + row) * HDIM + c4];
            *(float4*)&ws[row][c4] = w;
        }
        __syncthreads();
#pragma unroll 8
        for (int k = 0; k < 64; k++) {
            float xr0 = xs[2 * ty + 0][k];
            float xr1 = xs[2 * ty + 1][k];
            float4 wv = *(float4*)&ws[k][4 * tx];
            acc[0][0] = fmaf(xr0, wv.x, acc[0][0]);
            acc[0][1] = fmaf(xr0, wv.y, acc[0][1]);
            acc[0][2] = fmaf(xr0, wv.z, acc[0][2]);
            acc[0][3] = fmaf(xr0, wv.w, acc[0][3]);
            acc[1][0] = fmaf(xr1, wv.x, acc[1][0]);
            acc[1][1] = fmaf(xr1, wv.y, acc[1][1]);
            acc[1][2] = fmaf(xr1, wv.z, acc[1][2]);
            acc[1][3] = fmaf(xr1, wv.w, acc[1][3]);
        }
    }

    // epilogue: silu + dot with W2, partial over this thread's 4 cols
    float partial[2];
#pragma unroll
    for (int i = 0; i < 2; i++) {
        float p = 0.f;
#pragma unroll
        for (int j = 0; j < 4; j++) {
            float h = acc[i][j] + b1s[4 * tx + j];
            float s = h / (1.f + expf(-h));   // silu
            p = fmaf(s, w2s[4 * tx + j], p);
        }
        partial[i] = p;
    }
    __syncthreads();
#pragma unroll
    for (int i = 0; i < 2; i++) red[2 * ty + i][tx] = partial[i];
    __syncthreads();

    if (tid < 32) {
        float q = b2[0];
#pragma unroll
        for (int t = 0; t < 16; t++) q += red[tid][t];
        int ai = ab + tid;

        // batch dtype sniff: if int64, word n/2-1 is batch[n/2-1] in [0,B) -> hi==0.
        // if int32, it packs batch[n-2] | batch[n-1]<<32, batch[n-1]>0 (sorted).
        long long probe = ((const long long*)batch)[(n >> 1) - 1];
        int b = ((probe >> 32) == 0) ? (int)((const long long*)batch)[ai]
                                     : ((const int*)batch)[ai];
        g_batch[ai] = b;
        float px = pos[3 * ai], py = pos[3 * ai + 1], pz = pos[3 * ai + 2];
        g_pq[ai] = make_float4(px, py, pz, q);
        g_c[ai]  = fmaf(px, px, fmaf(py, py, pz * pz));
        atomicAdd(&sm_qsum[b], q);   // smem only; deterministic per block
    }
    __syncthreads();
    if (tid < MAXB)
        g_bsum[blockIdx.x][tid] = sm_qsum[tid];
}

// ---------------------------------------------------------------------------
// K_B: pair energies with fused neutralization.
// Block covers 32 atoms; each warp handles 4 consecutive atoms so every
// loaded j (float4 + |pj|^2) feeds 4 pair computations.
// r^2 expansion: r2 = |pi|^2 + soft^2 + |pj|^2 - 2 pi.pj  (1 add + 3 fma).
//   sum_j (q_j - mu) k_ij = (sum q_j k_ij) - mu (sum k_ij)
// Self pair included in loop, subtracted analytically afterwards.
// Prologue reduces g_bsum -> per-graph sums (replaces the memset node).
// ---------------------------------------------------------------------------
__global__ __launch_bounds__(256) void k_pairs(
    float* __restrict__ out,
    const float* __restrict__ scr_p, const float* __restrict__ soft_p,
    int n, int B)
{
    __shared__ float s_part[16][MAXB];
    __shared__ float s_qs[MAXB];
    __shared__ int   s_start[MAXB + 1];

    int tid = threadIdx.x;
    int nblk = n / 32;

    // stage 1: 256 threads -> 16 chunks x 16 graphs
    {
        int gg = tid & 15;
        int ch = tid >> 4;
        int chunk = (nblk + 15) >> 4;
        float s = 0.f;
        for (int k = 0; k < chunk; k++) {
            int b = ch * chunk + k;
            if (b < nblk) s += g_bsum[b][gg];
        }
        s_part[ch][gg] = s;
    }
    if (tid <= B) {
        if (tid == B) s_start[B] = n;
        else {
            int lo = 0, hi = n;          // lower_bound of graph id `tid`
            while (lo < hi) {
                int mid = (lo + hi) >> 1;
                if (g_batch[mid] < tid) lo = mid + 1; else hi = mid;
            }
            s_start[tid] = lo;
        }
    }
    __syncthreads();
    if (tid < MAXB) {
        float s = 0.f;
#pragma unroll
        for (int c = 0; c < 16; c++) s += s_part[c][tid];
        s_qs[tid] = s;
    }
    __syncthreads();

    int warp = tid >> 5;
    int lane = tid & 31;
    int i0 = blockIdx.x * 32 + warp * 4;   // this warp's 4 atoms
    if (i0 >= n) return;

    float scr  = scr_p[0];
    float soft = soft_p[0];
    float soft2 = soft * soft;
    float nls = -scr * 1.4426950408889634f;   // -scr * log2(e), for exp2f

    float aq[4] = {0.f, 0.f, 0.f, 0.f};
    float ak[4] = {0.f, 0.f, 0.f, 0.f};
    float qi[4], mu[4];
    int g0 = g_batch[i0];
    int g3 = g_batch[i0 + 3];

    if (g0 == g3) {
        // fast path: all 4 atoms share one segment
        int jlo = s_start[g0];
        int jhi = s_start[g0 + 1];
        float mean = s_qs[g0] / (float)(jhi - jlo);
        float m2x[4], m2y[4], m2z[4], ci[4];
#pragma unroll
        for (int k = 0; k < 4; k++) {
            float4 p = g_pq[i0 + k];
            qi[k] = p.w;  mu[k] = mean;
            m2x[k] = -2.f * p.x;  m2y[k] = -2.f * p.y;  m2z[k] = -2.f * p.z;
            ci[k] = g_c[i0 + k] + soft2;
        }
        for (int j = jlo + lane; j < jhi; j += 32) {
            float4 a = g_pq[j];
            float cj = g_c[j];
#pragma unroll
            for (int k = 0; k < 4; k++) {
                float r2 = fmaf(m2x[k], a.x,
                           fmaf(m2y[k], a.y,
                           fmaf(m2z[k], a.z, ci[k] + cj)));
                float ir = rsqrtf(r2);
                float e  = exp2f(nls * (r2 * ir));
                float kk = e * ir;
                aq[k] = fmaf(a.w, kk, aq[k]);
                ak[k] += kk;
            }
        }
    } else {
        // slow path: quad straddles a graph boundary (rare)
#pragma unroll
        for (int k = 0; k < 4; k++) {
            int i = i0 + k;
            float4 p = g_pq[i];
            int g = g_batch[i];
            int jlo = s_start[g];
            int jhi = s_start[g + 1];
            qi[k] = p.w;
            mu[k] = s_qs[g] / (float)(jhi - jlo);
            float m2x = -2.f * p.x, m2y = -2.f * p.y, m2z = -2.f * p.z;
            float ci = g_c[i] + soft2;
            for (int j = jlo + lane; j < jhi; j += 32) {
                float4 a = g_pq[j];
                float r2 = fmaf(m2x, a.x,
                           fmaf(m2y, a.y,
                           fmaf(m2z, a.z, ci + g_c[j])));
                float ir = rsqrtf(r2);
                float e  = exp2f(nls * (r2 * ir));
                float kk = e * ir;
                aq[k] = fmaf(a.w, kk, aq[k]);
                ak[k] += kk;
            }
        }
    }

#pragma unroll
    for (int k = 0; k < 4; k++) {
#pragma unroll
        for (int o = 16; o > 0; o >>= 1) {
            aq[k] += __shfl_xor_sync(0xffffffffu, aq[k], o);
            ak[k] += __shfl_xor_sync(0xffffffffu, ak[k], o);
        }
    }
    if (lane == 0) {
        // remove self pairs (r2 == soft2)
        float is = rsqrtf(soft2);
        float ks = exp2f(nls * (soft2 * is)) * is;
#pragma unroll
        for (int k = 0; k < 4; k++) {
            float a = aq[k] - qi[k] * ks;
            float b = ak[k] - ks;
            out[i0 + k] = 0.5f * (qi[k] - mu[k]) * (a - mu[k] * b);
        }
    }
}

// ---------------------------------------------------------------------------
// Launch sequence: exactly 2 kernel nodes (graph-capturable, allocation-free).
// Inputs (metadata order): x, pos, cell, W1, b1, W2, b2, screening, softening, batch
// ---------------------------------------------------------------------------
extern "C" void kernel_launch(void* const* d_in, const int* in_sizes, int n_in,
                              void* d_out, int out_size) {
    const float* x    = (const float*)d_in[0];
    const float* pos  = (const float*)d_in[1];
    // d_in[2] = cell (unused: nonperiodic)
    const float* W1   = (const float*)d_in[3];
    const float* b1   = (const float*)d_in[4];
    const float* W2   = (const float*)d_in[5];
    const float* b2   = (const float*)d_in[6];
    const float* scr  = (const float*)d_in[7];
    const float* soft = (const float*)d_in[8];
    const void*  batch = d_in[9];
    float* out = (float*)d_out;

    int n = in_sizes[0] / FDIM;   // 8192
    int B = in_sizes[2] / 9;      // 8 graphs (cell is [B,3,3])

    k_charge<<<n / 32, 256>>>(x, pos, W1, b1, W2, b2, batch, n);
    k_pairs<<<n / 32, 256>>>(out, scr, soft, n, B);
}